// round 11
// baseline (speedup 1.0000x reference)
#include <cuda_runtime.h>
#include <math.h>

// Problem shape (fixed by the dataset):
//   t: [16, 256, 128, 128] fp32
//   w_reduce: [256, 1024], b_reduce: [256]
//   w_expand: [1024, 256], b_expand: [1024]
// Output: same shape as t.

#define NB   16
#define NC   256
#define NSQ  256
#define NC4  1024         // 4*C
#define IMG_F4 4096       // 128*128/4 float4 per (b,c) image
#define IMG_F8 2048       // float8 (32B) chunks per image

// Images with index >= KEEP_THRESH are read with L2::evict_last in pass 1
// and consumed first (reverse order) by pass 2. 1536 imgs * 64KB = 96MB < 126MB L2.
#define KEEP_THRESH 2560

// Scratch (allocation-free rule: __device__ globals)
__device__ float g_means[NB * NC4];   // layout: [b][q*C + c]
__device__ float g_z    [NB * NSQ];   // layout: [b][j]
__device__ float g_gate [NB * NC4];   // layout: [b][q*C + c]

// ---- 256-bit (32B) loads with L2 eviction-policy hints ---------------------
// sm_103a ptxas only accepts L2::evict_* on .v8.b32 / .v4.b64 (256-bit) loads.
__device__ __forceinline__ void ldg256_evict_last(const void* p, float4& a, float4& b)
{
    unsigned long long x0, x1, x2, x3;
    asm volatile("ld.global.L2::evict_last.v4.b64 {%0,%1,%2,%3}, [%4];"
                 : "=l"(x0), "=l"(x1), "=l"(x2), "=l"(x3) : "l"(p));
    a.x = __uint_as_float((unsigned)(x0));       a.y = __uint_as_float((unsigned)(x0 >> 32));
    a.z = __uint_as_float((unsigned)(x1));       a.w = __uint_as_float((unsigned)(x1 >> 32));
    b.x = __uint_as_float((unsigned)(x2));       b.y = __uint_as_float((unsigned)(x2 >> 32));
    b.z = __uint_as_float((unsigned)(x3));       b.w = __uint_as_float((unsigned)(x3 >> 32));
}
__device__ __forceinline__ void ldg256_evict_first(const void* p, float4& a, float4& b)
{
    unsigned long long x0, x1, x2, x3;
    asm volatile("ld.global.L2::evict_first.v4.b64 {%0,%1,%2,%3}, [%4];"
                 : "=l"(x0), "=l"(x1), "=l"(x2), "=l"(x3) : "l"(p));
    a.x = __uint_as_float((unsigned)(x0));       a.y = __uint_as_float((unsigned)(x0 >> 32));
    a.z = __uint_as_float((unsigned)(x1));       a.w = __uint_as_float((unsigned)(x1 >> 32));
    b.x = __uint_as_float((unsigned)(x2));       b.y = __uint_as_float((unsigned)(x2 >> 32));
    b.z = __uint_as_float((unsigned)(x3));       b.w = __uint_as_float((unsigned)(x3 >> 32));
}

// ---------------------------------------------------------------------------
// Kernel 1: per-(b,c) quadrant means. 8 x 32B loads per thread.
// byte offset = tid*32 + k*8192  =>  row = tid/16 + 16k (k<4: top half),
// col float = (tid&15)*8 (left half iff (tid&15) < 8).
// Tail images (img >= KEEP_THRESH) loaded evict_last so they survive in L2
// for apply_gate's reverse-order consumption; head images evict_first.
// ---------------------------------------------------------------------------
__global__ __launch_bounds__(256) void quad_means_kernel(const float* __restrict__ t)
{
    const int img = blockIdx.x;                 // b*C + c
    const int tid = threadIdx.x;
    const char* __restrict__ p =
        reinterpret_cast<const char*>(t) + (size_t)img * (IMG_F4 * 16);

    float topS = 0.f, botS = 0.f;
    if (img >= KEEP_THRESH) {
#pragma unroll
        for (int k = 0; k < 8; ++k) {
            float4 a, b;
            ldg256_evict_last(p + tid * 32 + k * 8192, a, b);
            float s = ((a.x + a.y) + (a.z + a.w)) + ((b.x + b.y) + (b.z + b.w));
            if (k < 4) topS += s; else botS += s;
        }
    } else {
#pragma unroll
        for (int k = 0; k < 8; ++k) {
            float4 a, b;
            ldg256_evict_first(p + tid * 32 + k * 8192, a, b);
            float s = ((a.x + a.y) + (a.z + a.w)) + ((b.x + b.y) + (b.z + b.w));
            if (k < 4) topS += s; else botS += s;
        }
    }

    const bool right = (tid & 15) >= 8;

    __shared__ float sm[4 * 256];
    sm[0 * 256 + tid] = right ? 0.f : topS;   // q0: top-left
    sm[1 * 256 + tid] = right ? topS : 0.f;   // q1: top-right
    sm[2 * 256 + tid] = right ? 0.f : botS;   // q2: bot-left
    sm[3 * 256 + tid] = right ? botS : 0.f;   // q3: bot-right
    __syncthreads();

#pragma unroll
    for (int st = 128; st > 0; st >>= 1) {
        if (tid < st) {
#pragma unroll
            for (int q = 0; q < 4; ++q)
                sm[q * 256 + tid] += sm[q * 256 + tid + st];
        }
        __syncthreads();
    }

    if (tid < 4) {
        const int b = img >> 8;
        const int c = img & 255;
        g_means[b * NC4 + tid * NC + c] = sm[tid * 256] * (1.0f / 4096.0f);
    }
}

// ---------------------------------------------------------------------------
// Kernel 2a: z = mish(means @ w_reduce^T + b_reduce).
// PDL: weight rows loaded into registers BEFORE the dependency sync.
// Grid 32 x 256. Warp w owns output j = cta*8 + w; 16 per-batch accumulators,
// interleaved shfl reduce.
// ---------------------------------------------------------------------------
__global__ __launch_bounds__(256) void fc1_kernel(
    const float* __restrict__ w_reduce, const float* __restrict__ b_reduce)
{
    const int tid  = threadIdx.x;
    const int warp = tid >> 5;
    const int lane = tid & 31;

    const int j = blockIdx.x * 8 + warp;

    // ---- PDL prologue: independent of predecessor ----
    const float4* __restrict__ w =
        reinterpret_cast<const float4*>(w_reduce + (size_t)j * NC4);
    float4 wr[8];
#pragma unroll
    for (int i = 0; i < 8; ++i)
        wr[i] = w[lane + 32 * i];
    const float bj = b_reduce[j];

    // ---- wait for quad_means ----
    cudaGridDependencySynchronize();

    __shared__ float4 sm_m[NB * 256];     // all means: 16 x 1024 fp32 = 64KB
    {
        const float4* __restrict__ mp = reinterpret_cast<const float4*>(g_means);
#pragma unroll
        for (int i = 0; i < 16; ++i)
            sm_m[tid + i * 256] = mp[tid + i * 256];
    }
    __syncthreads();

    float acc[NB];
#pragma unroll
    for (int b = 0; b < NB; ++b) {
        float a = 0.f;
#pragma unroll
        for (int i = 0; i < 8; ++i) {
            float4 mv = sm_m[b * 256 + lane + 32 * i];
            a += wr[i].x * mv.x + wr[i].y * mv.y + wr[i].z * mv.z + wr[i].w * mv.w;
        }
        acc[b] = a;
    }

#pragma unroll
    for (int o = 16; o > 0; o >>= 1) {
#pragma unroll
        for (int b = 0; b < NB; ++b)
            acc[b] += __shfl_xor_sync(0xFFFFFFFFu, acc[b], o);
    }

    if (lane == 0) {
#pragma unroll
        for (int b = 0; b < NB; ++b) {
            float x = acc[b] + bj;
            float sp = (x > 20.0f) ? x : log1pf(expf(x));
            g_z[b * NSQ + j] = x * tanhf(sp);
        }
    }
}

// ---------------------------------------------------------------------------
// Kernel 2b: gate = sigmoid(z @ w_expand^T + b_expand).
// Grid 128 x 256: warp-per-output, 16 per-batch accumulators, interleaved
// reduce. Weight rows loaded pre-sync (PDL prologue).
// ---------------------------------------------------------------------------
__global__ __launch_bounds__(256) void fc2_kernel(
    const float* __restrict__ w_expand, const float* __restrict__ b_expand)
{
    const int tid  = threadIdx.x;
    const int warp = tid >> 5;
    const int lane = tid & 31;

    const int j = blockIdx.x * 8 + warp;

    // ---- PDL prologue ----
    const float4* __restrict__ w =
        reinterpret_cast<const float4*>(w_expand + (size_t)j * NSQ);
    float4 w0 = w[lane];
    float4 w1 = w[lane + 32];
    const float bj = b_expand[j];

    // ---- wait for fc1 ----
    cudaGridDependencySynchronize();

    __shared__ float4 sm_z[NB * 64];      // all z: 16 x 256 fp32 = 16KB
    {
        const float4* __restrict__ zp = reinterpret_cast<const float4*>(g_z);
#pragma unroll
        for (int i = 0; i < 4; ++i)
            sm_z[tid + i * 256] = zp[tid + i * 256];
    }
    __syncthreads();

    float acc[NB];
#pragma unroll
    for (int b = 0; b < NB; ++b) {
        float4 z0 = sm_z[b * 64 + lane];
        float4 z1 = sm_z[b * 64 + lane + 32];
        acc[b] = w0.x * z0.x + w0.y * z0.y + w0.z * z0.z + w0.w * z0.w
               + w1.x * z1.x + w1.y * z1.y + w1.z * z1.z + w1.w * z1.w;
    }

#pragma unroll
    for (int o = 16; o > 0; o >>= 1) {
#pragma unroll
        for (int b = 0; b < NB; ++b)
            acc[b] += __shfl_xor_sync(0xFFFFFFFFu, acc[b], o);
    }

    if (lane == 0) {
#pragma unroll
        for (int b = 0; b < NB; ++b)
            g_gate[b * NC4 + j] = 1.0f / (1.0f + expf(-acc[b] - bj));
    }
}

// ---------------------------------------------------------------------------
// Kernel 3: out = t * gate. 2 x 32B evict_first loads per thread (float8
// units; base8 = cta*512 + tid, stride 256). CTA covers a 32-row-aligned
// window of one image => both loads share (b, c, quadrant). REVERSE traversal
// consumes the evict_last tail first (L2 hits). PDL prefetch pre-sync.
// ---------------------------------------------------------------------------
__global__ __launch_bounds__(256) void apply_gate_kernel(
    const float* __restrict__ t, float* __restrict__ out)
{
    const int cta   = gridDim.x - 1 - blockIdx.x;       // descending order
    const int base8 = cta * 512 + threadIdx.x;          // float8 (32B) index

    const char* __restrict__ tp = reinterpret_cast<const char*>(t);
    float4* __restrict__ op     = reinterpret_cast<float4*>(out);

    // ---- PDL prologue: prefetch t (independent of gate) ----
    float4 a0, b0, a1, b1;
    ldg256_evict_first(tp + (size_t)base8 * 32, a0, b0);
    ldg256_evict_first(tp + (size_t)(base8 + 256) * 32, a1, b1);

    // ---- wait for fc2 ----
    cudaGridDependencySynchronize();

    const int img     = base8 >> 11;           // / IMG_F8
    const int within8 = base8 & (IMG_F8 - 1);
    const int row     = within8 >> 4;          // 16 float8 per row
    const int col8    = within8 & 15;
    const int q       = ((row >= 64) ? 2 : 0) | ((col8 >= 8) ? 1 : 0);
    const int b       = img >> 8;
    const int c       = img & 255;

    const float gv = __ldg(&g_gate[b * NC4 + q * NC + c]);

    a0.x *= gv; a0.y *= gv; a0.z *= gv; a0.w *= gv;
    b0.x *= gv; b0.y *= gv; b0.z *= gv; b0.w *= gv;
    a1.x *= gv; a1.y *= gv; a1.z *= gv; a1.w *= gv;
    b1.x *= gv; b1.y *= gv; b1.z *= gv; b1.w *= gv;

    __stcs(op + (size_t)base8 * 2,           a0);
    __stcs(op + (size_t)base8 * 2 + 1,       b0);
    __stcs(op + (size_t)(base8 + 256) * 2,   a1);
    __stcs(op + (size_t)(base8 + 256) * 2 + 1, b1);
}

// ---------------------------------------------------------------------------
static void launch_pdl(void* func, dim3 grid, dim3 block, void** args)
{
    cudaLaunchConfig_t cfg = {};
    cfg.gridDim  = grid;
    cfg.blockDim = block;
    cudaLaunchAttribute attr[1];
    attr[0].id = cudaLaunchAttributeProgrammaticStreamSerialization;
    attr[0].val.programmaticStreamSerializationAllowed = 1;
    cfg.attrs = attr;
    cfg.numAttrs = 1;
    cudaLaunchKernelExC(&cfg, func, args);
}

extern "C" void kernel_launch(void* const* d_in, const int* in_sizes, int n_in,
                              void* d_out, int out_size)
{
    const float* t        = (const float*)d_in[0];
    const float* w_reduce = (const float*)d_in[1];
    const float* b_reduce = (const float*)d_in[2];
    const float* w_expand = (const float*)d_in[3];
    const float* b_expand = (const float*)d_in[4];
    float* out            = (float*)d_out;

    // Pass 1: quadrant means (4096 CTAs), tail pinned-ish in L2
    quad_means_kernel<<<NB * NC, 256>>>(t);

    // FC chain + apply, PDL-chained.
    {
        void* args[] = {(void*)&w_reduce, (void*)&b_reduce};
        launch_pdl((void*)fc1_kernel, dim3(32), dim3(256), args);
    }
    {
        void* args[] = {(void*)&w_expand, (void*)&b_expand};
        launch_pdl((void*)fc2_kernel, dim3(128), dim3(256), args);
    }
    {
        void* args[] = {(void*)&t, (void*)&out};
        const int total_f8 = NB * NC * IMG_F8;   // 8388608
        dim3 grid(total_f8 / 512);               // 16384
        launch_pdl((void*)apply_gate_kernel, grid, dim3(256), args);
    }
}

// round 12
// speedup vs baseline: 1.0105x; 1.0105x over previous
#include <cuda_runtime.h>
#include <math.h>

// Problem shape (fixed by the dataset):
//   t: [16, 256, 128, 128] fp32
//   w_reduce: [256, 1024], b_reduce: [256]
//   w_expand: [1024, 256], b_expand: [1024]
// Output: same shape as t.

#define NB   16
#define NC   256
#define NSQ  256
#define NC4  1024         // 4*C
#define IMG_F4 4096       // 128*128/4 float4 per (b,c) image

// Scratch (allocation-free rule: __device__ globals)
__device__ float g_means[NB * NC4];   // layout: [b][q*C + c]
__device__ float g_z    [NB * NSQ];   // layout: [b][j]
__device__ float g_gate [NB * NC4];   // layout: [b][q*C + c]

// ---------------------------------------------------------------------------
// Kernel 1: per-(b,c) quadrant means. (R9 config: 41.5us @ 82.9% DRAM.)
// Early PDL trigger: fc1's pre-sync work (weight prefetch) is independent of
// this kernel, so let it launch immediately.
// ---------------------------------------------------------------------------
__global__ __launch_bounds__(256) void quad_means_kernel(const float* __restrict__ t)
{
    cudaTriggerProgrammaticLaunchCompletion();

    const int img = blockIdx.x;                 // b*C + c
    const int tid = threadIdx.x;
    const float4* __restrict__ p =
        reinterpret_cast<const float4*>(t) + (size_t)img * IMG_F4;

    float topS = 0.f, botS = 0.f;
#pragma unroll
    for (int k = 0; k < 16; ++k) {
        float4 v = p[tid + k * 256];
        float s = (v.x + v.y) + (v.z + v.w);
        if (k < 8) topS += s; else botS += s;
    }

    const bool right = (tid & 31) >= 16;

    __shared__ float sm[4 * 256];
    sm[0 * 256 + tid] = right ? 0.f : topS;   // q0: top-left
    sm[1 * 256 + tid] = right ? topS : 0.f;   // q1: top-right
    sm[2 * 256 + tid] = right ? 0.f : botS;   // q2: bot-left
    sm[3 * 256 + tid] = right ? botS : 0.f;   // q3: bot-right
    __syncthreads();

#pragma unroll
    for (int st = 128; st > 0; st >>= 1) {
        if (tid < st) {
#pragma unroll
            for (int q = 0; q < 4; ++q)
                sm[q * 256 + tid] += sm[q * 256 + tid + st];
        }
        __syncthreads();
    }

    if (tid < 4) {
        const int b = img >> 8;
        const int c = img & 255;
        g_means[b * NC4 + tid * NC + c] = sm[tid * 256] * (1.0f / 4096.0f);
    }
}

// ---------------------------------------------------------------------------
// Kernel 2a: z = mish(means @ w_reduce^T + b_reduce).
// PDL: weight rows loaded into registers BEFORE the dependency sync.
// Grid 32 x 256. Warp w owns output j = cta*8 + w; 16 per-batch accumulators,
// interleaved shfl reduce. Early trigger after staging so fc2 launches ASAP.
// ---------------------------------------------------------------------------
__global__ __launch_bounds__(256) void fc1_kernel(
    const float* __restrict__ w_reduce, const float* __restrict__ b_reduce)
{
    const int tid  = threadIdx.x;
    const int warp = tid >> 5;
    const int lane = tid & 31;

    const int j = blockIdx.x * 8 + warp;

    // ---- PDL prologue: independent of predecessor ----
    const float4* __restrict__ w =
        reinterpret_cast<const float4*>(w_reduce + (size_t)j * NC4);
    float4 wr[8];
#pragma unroll
    for (int i = 0; i < 8; ++i)
        wr[i] = w[lane + 32 * i];
    const float bj = b_reduce[j];

    // ---- wait for quad_means ----
    cudaGridDependencySynchronize();

    __shared__ float4 sm_m[NB * 256];     // all means: 16 x 1024 fp32 = 64KB
    {
        const float4* __restrict__ mp = reinterpret_cast<const float4*>(g_means);
#pragma unroll
        for (int i = 0; i < 16; ++i)
            sm_m[tid + i * 256] = mp[tid + i * 256];
    }
    __syncthreads();

    cudaTriggerProgrammaticLaunchCompletion();

    float acc[NB];
#pragma unroll
    for (int b = 0; b < NB; ++b) {
        float a = 0.f;
#pragma unroll
        for (int i = 0; i < 8; ++i) {
            float4 mv = sm_m[b * 256 + lane + 32 * i];
            a += wr[i].x * mv.x + wr[i].y * mv.y + wr[i].z * mv.z + wr[i].w * mv.w;
        }
        acc[b] = a;
    }

#pragma unroll
    for (int o = 16; o > 0; o >>= 1) {
#pragma unroll
        for (int b = 0; b < NB; ++b)
            acc[b] += __shfl_xor_sync(0xFFFFFFFFu, acc[b], o);
    }

    if (lane == 0) {
#pragma unroll
        for (int b = 0; b < NB; ++b) {
            float x = acc[b] + bj;
            float sp = (x > 20.0f) ? x : log1pf(expf(x));
            g_z[b * NSQ + j] = x * tanhf(sp);
        }
    }
}

// ---------------------------------------------------------------------------
// Kernel 2b: gate = sigmoid(z @ w_expand^T + b_expand).
// Grid 128 x 256: warp-per-output, 16 per-batch accumulators, interleaved
// reduce. Weight rows loaded pre-sync. Early trigger after staging so
// apply_gate launches (and prefetches t) during the gate compute.
// ---------------------------------------------------------------------------
__global__ __launch_bounds__(256) void fc2_kernel(
    const float* __restrict__ w_expand, const float* __restrict__ b_expand)
{
    const int tid  = threadIdx.x;
    const int warp = tid >> 5;
    const int lane = tid & 31;

    const int j = blockIdx.x * 8 + warp;

    // ---- PDL prologue ----
    const float4* __restrict__ w =
        reinterpret_cast<const float4*>(w_expand + (size_t)j * NSQ);
    float4 w0 = w[lane];
    float4 w1 = w[lane + 32];
    const float bj = b_expand[j];

    // ---- wait for fc1 ----
    cudaGridDependencySynchronize();

    __shared__ float4 sm_z[NB * 64];      // all z: 16 x 256 fp32 = 16KB
    {
        const float4* __restrict__ zp = reinterpret_cast<const float4*>(g_z);
#pragma unroll
        for (int i = 0; i < 4; ++i)
            sm_z[tid + i * 256] = zp[tid + i * 256];
    }
    __syncthreads();

    cudaTriggerProgrammaticLaunchCompletion();

    float acc[NB];
#pragma unroll
    for (int b = 0; b < NB; ++b) {
        float4 z0 = sm_z[b * 64 + lane];
        float4 z1 = sm_z[b * 64 + lane + 32];
        acc[b] = w0.x * z0.x + w0.y * z0.y + w0.z * z0.z + w0.w * z0.w
               + w1.x * z1.x + w1.y * z1.y + w1.z * z1.z + w1.w * z1.w;
    }

#pragma unroll
    for (int o = 16; o > 0; o >>= 1) {
#pragma unroll
        for (int b = 0; b < NB; ++b)
            acc[b] += __shfl_xor_sync(0xFFFFFFFFu, acc[b], o);
    }

    if (lane == 0) {
#pragma unroll
        for (int b = 0; b < NB; ++b)
            g_gate[b * NC4 + j] = 1.0f / (1.0f + expf(-acc[b] - bj));
    }
}

// ---------------------------------------------------------------------------
// Kernel 3: out = t * gate. 8 float4 per thread, strided by 256 within a
// 2048-float4 block (grid 8192). 2048 | 4096 => a CTA covers a 64-row
// (one vertical half) window of a single image; col4 = tid&31 fixed.
// All 8 accesses share (b, c, quadrant). PDL: all 8 t-loads issue pre-sync
// (t independent of gate) — 32KB/CTA prefetched while fc1/fc2 run.
// REVERSE traversal (R9: consumes quad_means' L2 tail first). Streaming
// stores to limit pollution.
// ---------------------------------------------------------------------------
__global__ __launch_bounds__(256) void apply_gate_kernel(
    const float* __restrict__ t, float* __restrict__ out)
{
    const int cta  = gridDim.x - 1 - blockIdx.x;        // descending order
    const int base = cta * 2048 + threadIdx.x;          // float4 index

    const float4* __restrict__ tp = reinterpret_cast<const float4*>(t);
    float4* __restrict__ op       = reinterpret_cast<float4*>(out);

    // ---- PDL prologue: prefetch t (independent of gate) ----
    float4 v[8];
#pragma unroll
    for (int k = 0; k < 8; ++k)
        v[k] = tp[base + k * 256];

    // ---- wait for fc2 ----
    cudaGridDependencySynchronize();

    const int img    = base >> 12;
    const int within = base & (IMG_F4 - 1);
    const int col4   = within & 31;
    const int q      = ((within >= 2048) ? 2 : 0) | ((col4 >= 16) ? 1 : 0);
    const int b      = img >> 8;
    const int c      = img & 255;

    const float gv = __ldg(&g_gate[b * NC4 + q * NC + c]);

#pragma unroll
    for (int k = 0; k < 8; ++k) {
        v[k].x *= gv; v[k].y *= gv; v[k].z *= gv; v[k].w *= gv;
        __stcs(op + base + k * 256, v[k]);
    }
}

// ---------------------------------------------------------------------------
static void launch_pdl(void* func, dim3 grid, dim3 block, void** args)
{
    cudaLaunchConfig_t cfg = {};
    cfg.gridDim  = grid;
    cfg.blockDim = block;
    cudaLaunchAttribute attr[1];
    attr[0].id = cudaLaunchAttributeProgrammaticStreamSerialization;
    attr[0].val.programmaticStreamSerializationAllowed = 1;
    cfg.attrs = attr;
    cfg.numAttrs = 1;
    cudaLaunchKernelExC(&cfg, func, args);
}

extern "C" void kernel_launch(void* const* d_in, const int* in_sizes, int n_in,
                              void* d_out, int out_size)
{
    const float* t        = (const float*)d_in[0];
    const float* w_reduce = (const float*)d_in[1];
    const float* b_reduce = (const float*)d_in[2];
    const float* w_expand = (const float*)d_in[3];
    const float* b_expand = (const float*)d_in[4];
    float* out            = (float*)d_out;

    // Pass 1: quadrant means (4096 CTAs) — R9 config, 41.5us @ 82.9% DRAM
    quad_means_kernel<<<NB * NC, 256>>>(t);

    // FC chain + apply, PDL-chained with early triggers.
    {
        void* args[] = {(void*)&w_reduce, (void*)&b_reduce};
        launch_pdl((void*)fc1_kernel, dim3(32), dim3(256), args);
    }
    {
        void* args[] = {(void*)&w_expand, (void*)&b_expand};
        launch_pdl((void*)fc2_kernel, dim3(128), dim3(256), args);
    }
    {
        void* args[] = {(void*)&t, (void*)&out};
        const int total_f4 = NB * NC * IMG_F4;   // 16777216
        dim3 grid(total_f4 / 2048);              // 8192
        launch_pdl((void*)apply_gate_kernel, grid, dim3(256), args);
    }
}